// round 14
// baseline (speedup 1.0000x reference)
#include <cuda_runtime.h>

// Sum-reduce 20M fp32 values (full sparse sum == values.sum(); indices unused).
// HBM-bound streaming read of 80 MB. Single fused kernel (last-block-counter
// finalize). R13: 8-way strided unroll, independent accumulators, 32-bit
// hot-loop indexing (R12's win: alu% 9.6->2.5, DRAM% 61.1). 512 threads x 592
// blocks = one full-occupancy wave.

__device__ float         g_partial = 0.0f;
__device__ unsigned int  g_count   = 0;

__global__ void __launch_bounds__(512) sum_kernel(const float* __restrict__ vals,
                                                  long long n, float* __restrict__ out,
                                                  int nblocks) {
    unsigned int n4 = (unsigned int)(n >> 2);  // number of float4s (5M, fits u32)
    const float4* v4 = reinterpret_cast<const float4*>(vals);

    unsigned int idx    = blockIdx.x * blockDim.x + threadIdx.x;
    unsigned int stride = gridDim.x * blockDim.x;

    float a0 = 0.0f, a1 = 0.0f, a2 = 0.0f, a3 = 0.0f;
    float a4 = 0.0f, a5 = 0.0f, a6 = 0.0f, a7 = 0.0f;

    unsigned int i = idx;
    for (; i + 7u * stride < n4; i += 8u * stride) {
        float4 v0 = v4[i];
        float4 v1 = v4[i + stride];
        float4 v2 = v4[i + 2u * stride];
        float4 v3 = v4[i + 3u * stride];
        float4 v4r = v4[i + 4u * stride];
        float4 v5 = v4[i + 5u * stride];
        float4 v6 = v4[i + 6u * stride];
        float4 v7 = v4[i + 7u * stride];
        a0 += (v0.x + v0.y) + (v0.z + v0.w);
        a1 += (v1.x + v1.y) + (v1.z + v1.w);
        a2 += (v2.x + v2.y) + (v2.z + v2.w);
        a3 += (v3.x + v3.y) + (v3.z + v3.w);
        a4 += (v4r.x + v4r.y) + (v4r.z + v4r.w);
        a5 += (v5.x + v5.y) + (v5.z + v5.w);
        a6 += (v6.x + v6.y) + (v6.z + v6.w);
        a7 += (v7.x + v7.y) + (v7.z + v7.w);
    }
    for (; i < n4; i += stride) {
        float4 v = v4[i];
        a0 += (v.x + v.y) + (v.z + v.w);
    }
    // scalar tail (n not divisible by 4)
    for (long long j = ((long long)n4 << 2) + idx; j < n; j += stride) {
        a0 += vals[j];
    }

    float acc = ((a0 + a1) + (a2 + a3)) + ((a4 + a5) + (a6 + a7));

    // warp reduce
    #pragma unroll
    for (int off = 16; off > 0; off >>= 1)
        acc += __shfl_down_sync(0xFFFFFFFFu, acc, off);

    __shared__ float warp_sums[16];  // 512 threads = 16 warps
    int lane = threadIdx.x & 31;
    int wid  = threadIdx.x >> 5;
    if (lane == 0) warp_sums[wid] = acc;
    __syncthreads();

    if (wid == 0) {
        float s = (lane < 16) ? warp_sums[lane] : 0.0f;
        #pragma unroll
        for (int off = 8; off > 0; off >>= 1)
            s += __shfl_down_sync(0xFFFFFFFFu, s, off);

        if (lane == 0) {
            atomicAdd(&g_partial, s);
            __threadfence();
            unsigned int done = atomicAdd(&g_count, 1u);
            if (done == (unsigned int)nblocks - 1u) {
                // last block: publish result and reset scratch for next replay
                out[0]    = g_partial;
                g_partial = 0.0f;
                g_count   = 0u;
            }
        }
    }
}

extern "C" void kernel_launch(void* const* d_in, const int* in_sizes, int n_in,
                              void* d_out, int out_size) {
    const float* vals = (const float*)d_in[0];
    long long n = (long long)in_sizes[0];
    float* out = (float*)d_out;

    int grid = 148 * 4;  // 592 blocks x 512 threads = one full-occupancy wave
    sum_kernel<<<grid, 512>>>(vals, n, out, grid);
}

// round 15
// speedup vs baseline: 1.2069x; 1.2069x over previous
#include <cuda_runtime.h>

// Sum-reduce 20M fp32 values (full sparse sum == values.sum(); indices unused).
// HBM-bound streaming read of 80 MB. Single fused kernel (last-block-counter
// finalize). R15 = exact revert to R12, the measured optimum:
//   - 4-way strided unroll, independent accumulators. MLP_p1=4 at oe=4 CTAs/SM
//     sits exactly at the L1tex-queue knee (oe*MLP=16): R13's 8-way (oe*MLP=32)
//     regressed 11.7->15.7us via cross-CTA queue contention; __ldcs regressed
//     earlier (R5). Do not touch either.
//   - 32-bit hot-loop indexing (alu% 9.6 -> 2.5).
//   - 512 threads x 592 blocks = exactly one full-occupancy wave.
// 11.71 us = ~6.8 TB/s wall, ~85% of HBM3e spec.

__device__ float         g_partial = 0.0f;
__device__ unsigned int  g_count   = 0;

__global__ void __launch_bounds__(512) sum_kernel(const float* __restrict__ vals,
                                                  long long n, float* __restrict__ out,
                                                  int nblocks) {
    unsigned int n4 = (unsigned int)(n >> 2);  // number of float4s (5M, fits u32)
    const float4* v4 = reinterpret_cast<const float4*>(vals);

    unsigned int idx    = blockIdx.x * blockDim.x + threadIdx.x;
    unsigned int stride = gridDim.x * blockDim.x;

    float a0 = 0.0f, a1 = 0.0f, a2 = 0.0f, a3 = 0.0f;

    unsigned int i = idx;
    for (; i + 3u * stride < n4; i += 4u * stride) {
        float4 v0 = v4[i];
        float4 v1 = v4[i + stride];
        float4 v2 = v4[i + 2u * stride];
        float4 v3 = v4[i + 3u * stride];
        a0 += (v0.x + v0.y) + (v0.z + v0.w);
        a1 += (v1.x + v1.y) + (v1.z + v1.w);
        a2 += (v2.x + v2.y) + (v2.z + v2.w);
        a3 += (v3.x + v3.y) + (v3.z + v3.w);
    }
    for (; i < n4; i += stride) {
        float4 v = v4[i];
        a0 += (v.x + v.y) + (v.z + v.w);
    }
    // scalar tail (n not divisible by 4)
    for (long long j = ((long long)n4 << 2) + idx; j < n; j += stride) {
        a0 += vals[j];
    }

    float acc = (a0 + a1) + (a2 + a3);

    // warp reduce
    #pragma unroll
    for (int off = 16; off > 0; off >>= 1)
        acc += __shfl_down_sync(0xFFFFFFFFu, acc, off);

    __shared__ float warp_sums[16];  // 512 threads = 16 warps
    int lane = threadIdx.x & 31;
    int wid  = threadIdx.x >> 5;
    if (lane == 0) warp_sums[wid] = acc;
    __syncthreads();

    if (wid == 0) {
        float s = (lane < 16) ? warp_sums[lane] : 0.0f;
        #pragma unroll
        for (int off = 8; off > 0; off >>= 1)
            s += __shfl_down_sync(0xFFFFFFFFu, s, off);

        if (lane == 0) {
            atomicAdd(&g_partial, s);
            __threadfence();
            unsigned int done = atomicAdd(&g_count, 1u);
            if (done == (unsigned int)nblocks - 1u) {
                // last block: publish result and reset scratch for next replay
                out[0]    = g_partial;
                g_partial = 0.0f;
                g_count   = 0u;
            }
        }
    }
}

extern "C" void kernel_launch(void* const* d_in, const int* in_sizes, int n_in,
                              void* d_out, int out_size) {
    const float* vals = (const float*)d_in[0];
    long long n = (long long)in_sizes[0];
    float* out = (float*)d_out;

    int grid = 148 * 4;  // 592 blocks x 512 threads = one full-occupancy wave
    sum_kernel<<<grid, 512>>>(vals, n, out, grid);
}